// round 3
// baseline (speedup 1.0000x reference)
#include <cuda_runtime.h>
#include <math.h>

#define BB 2048
#define CC 3
#define TT 300
#define JJ 25
#define TJ (TT * JJ)            // 7500 elements per (b,c) slice
#define NSLICE (BB * CC)        // 6144 slices
#define WPB 8                   // warps per block (1 warp = 1 slice)
#define NBLK (NSLICE / WPB)     // 768 blocks
#define NTHREADS (WPB * 32)

// Global accumulators (allocation-free scratch). Zero-initialized at load;
// the last finishing block resets them, so every kernel_launch invocation
// (and every graph replay) starts from zero. Deterministic.
__device__ double g_rec = 0.0;
__device__ double g_smooth = 0.0;
__device__ unsigned int g_count = 0u;

__global__ void __launch_bounds__(NTHREADS)
loss_kernel(const float* __restrict__ x, const float* __restrict__ tg,
            float* __restrict__ out) {
    const int warp = threadIdx.x >> 5;
    const int lane = threadIdx.x & 31;
    const int slice = blockIdx.x * WPB + warp;          // < 6144

    const float* __restrict__ xs = x  + (size_t)slice * TJ;
    const float* __restrict__ ts = tg + (size_t)slice * TJ;

    const bool active = (lane < JJ);

    float accd = 0.0f;   // (sx - st) for joint j = lane
    float rec  = 0.0f;   // sum of (x - t)^2 over this lane's elements

    #pragma unroll 4
    for (int t = 0; t < TT; t++) {
        float xf = 0.0f, tf = 0.0f;
        if (active) {
            xf = __ldg(xs + t * JJ + lane);
            tf = __ldg(ts + t * JJ + lane);
        }
        const float d = xf - tf;
        rec = fmaf(d, d, rec);

        // element at frame t contributes +x to sx if t < T-1,
        // and -x^2 to sx if t > 0 (targets negated).
        float c = (t < TT - 1) ? d : 0.0f;
        if (t > 0) c -= (xf * xf - tf * tf);
        accd += c;
    }

    // Warp reduction: smooth uses joints 0..J-2 only (lanes 0..23).
    float av = (lane < JJ - 1) ? fabsf(accd) : 0.0f;
    #pragma unroll
    for (int o = 16; o > 0; o >>= 1) {
        av  += __shfl_xor_sync(0xffffffffu, av,  o);
        rec += __shfl_xor_sync(0xffffffffu, rec, o);
    }

    __shared__ double s_rec[WPB];
    __shared__ double s_sm[WPB];
    if (lane == 0) {
        s_rec[warp] = (double)rec;
        s_sm[warp]  = sqrt((double)av) / (double)TJ;
    }
    __syncthreads();

    if (threadIdx.x == 0) {
        double rtot = 0.0, stot = 0.0;
        #pragma unroll
        for (int w = 0; w < WPB; w++) { rtot += s_rec[w]; stot += s_sm[w]; }
        atomicAdd(&g_rec, rtot);
        atomicAdd(&g_smooth, stot);
        __threadfence();
        const unsigned int ticket = atomicAdd(&g_count, 1u);
        if (ticket == NBLK - 1) {
            // All other blocks' adds are visible (they fenced before their
            // ticket increment). Atomic reads bypass any stale L1 line.
            const double rec_sum = atomicAdd(&g_rec, 0.0);
            const double sm_sum  = atomicAdd(&g_smooth, 0.0);
            const double rec_mean    = rec_sum / ((double)BB * CC * TT * JJ);
            const double smooth_mean = sm_sum  / ((double)BB * CC);
            out[0] = (float)(2.0 * rec_mean + 3.0 * smooth_mean);
            // Reset for the next invocation / graph replay.
            g_rec = 0.0;
            g_smooth = 0.0;
            __threadfence();
            g_count = 0u;
        }
    }
}

extern "C" void kernel_launch(void* const* d_in, const int* in_sizes, int n_in,
                              void* d_out, int out_size) {
    const float* x  = (const float*)d_in[0];
    const float* tg = (const float*)d_in[1];
    float* out = (float*)d_out;

    loss_kernel<<<NBLK, NTHREADS>>>(x, tg, out);
}